// round 12
// baseline (speedup 1.0000x reference)
#include <cuda_runtime.h>
#include <math.h>

// ---------------------------------------------------------------------------
// VQ-VAE forward, fp32. Round 12: conv3h_k = half-row (16-row) variant of the
// smem-staged 3x3 conv -> grid 2048 (occ 36%->~70%+) for e3/d1/res convs.
// Rest identical to R11.
// Output layout: [loss, x_recon(1572864), perplexity]
// ---------------------------------------------------------------------------

// Scratch (device globals; no allocation allowed)
__device__ float g_A[32u * 64 * 64 * 64];    // e1 out / dt1 out / res partials
__device__ float g_B[32u * 128 * 32 * 32];   // e2 out
__device__ float g_C[32u * 128 * 32 * 32];   // e3 out + encoder res stack
__device__ float g_Z[32u * 64 * 32 * 32];    // pre-VQ z
__device__ float g_Q[32u * 64 * 32 * 32];    // quantized q
__device__ float g_G[32u * 128 * 32 * 32];   // decoder stack
__device__ int   g_idx[32768];
__device__ float g_cnorm[512];
__device__ float g_err[32768];

// ---------------------------------------------------------------------------
// Generic direct conv (R2, proven): used for e1 (k4s2) and pre (1x1).
// ---------------------------------------------------------------------------
template <int KH, int KW, int S, int P, int TCO,
          int CIN, int HIN, int WIN, int COUT, int HOUT, int WOUT,
          bool IN_RELU, bool OUT_RELU, bool BIAS, bool ADD>
__global__ __launch_bounds__(128)
void conv_k(const float* __restrict__ in, const float* __restrict__ wt,
            const float* __restrict__ bs, float* __restrict__ out,
            const float* __restrict__ res)
{
    constexpr int TX   = 8;
    constexpr int WINW = (TX - 1) * S + KW;
    static_assert((HOUT * WOUT / TX) % 128 == 0, "tiles fill blocks");

    int tid = blockIdx.x * 128 + threadIdx.x;
    int ox0 = (tid * TX) % WOUT;
    int oy  = (tid * TX) / WOUT;
    int co0 = blockIdx.y * TCO;
    int b   = blockIdx.z;

    float acc[TCO][TX];
#pragma unroll
    for (int c = 0; c < TCO; c++) {
        float bv = BIAS ? __ldg(bs + co0 + c) : 0.f;
#pragma unroll
        for (int j = 0; j < TX; j++) acc[c][j] = bv;
    }

    const float* inb = in + (size_t)b * CIN * HIN * WIN;
    const int ixb = ox0 * S - P;

#pragma unroll 1
    for (int ci = 0; ci < CIN; ci++) {
        const float* ip  = inb + ci * HIN * WIN;
        const float* wci = wt + ((size_t)co0 * CIN + ci) * KH * KW;
#pragma unroll
        for (int ky = 0; ky < KH; ky++) {
            int iy = oy * S - P + ky;
            if (P > 0 && (iy < 0 || iy >= HIN)) continue;
            const float* row = ip + iy * WIN;
            float w[WINW];
            if constexpr (P == 0) {
                float4 v0 = *(const float4*)(row + ox0);
                float4 v1 = *(const float4*)(row + ox0 + 4);
                w[0] = v0.x; w[1] = v0.y; w[2] = v0.z; w[3] = v0.w;
                w[4] = v1.x; w[5] = v1.y; w[6] = v1.z; w[7] = v1.w;
            } else {
                w[0] = (ixb >= 0) ? row[ixb] : 0.f;
#pragma unroll
                for (int m = 0; m < (WINW - 2) / 4; m++) {
                    float4 v = *(const float4*)(row + ixb + 1 + 4 * m);
                    w[1 + 4 * m] = v.x; w[2 + 4 * m] = v.y;
                    w[3 + 4 * m] = v.z; w[4 + 4 * m] = v.w;
                }
                w[WINW - 1] = (ixb + WINW - 1 < WIN) ? row[ixb + WINW - 1] : 0.f;
            }
            if (IN_RELU) {
#pragma unroll
                for (int m = 0; m < WINW; m++) w[m] = fmaxf(w[m], 0.f);
            }
#pragma unroll
            for (int c = 0; c < TCO; c++) {
                const float* wp = wci + c * CIN * KH * KW + ky * KW;
                if constexpr (KW == 4) {
                    float4 wv = *(const float4*)wp;
                    float wk[4] = {wv.x, wv.y, wv.z, wv.w};
#pragma unroll
                    for (int kx = 0; kx < 4; kx++)
#pragma unroll
                        for (int j = 0; j < TX; j++)
                            acc[c][j] = fmaf(w[j * S + kx], wk[kx], acc[c][j]);
                } else {
#pragma unroll
                    for (int kx = 0; kx < KW; kx++) {
                        float wv = __ldg(wp + kx);
#pragma unroll
                        for (int j = 0; j < TX; j++)
                            acc[c][j] = fmaf(w[j * S + kx], wv, acc[c][j]);
                    }
                }
            }
        }
    }

#pragma unroll
    for (int c = 0; c < TCO; c++) {
        size_t o = (((size_t)b * COUT + (co0 + c)) * HOUT + oy) * WOUT + ox0;
        float v[TX];
#pragma unroll
        for (int j = 0; j < TX; j++) v[j] = acc[c][j];
        if (ADD) {
            float4 r0 = *(const float4*)(res + o);
            float4 r1 = *(const float4*)(res + o + 4);
            v[0] += r0.x; v[1] += r0.y; v[2] += r0.z; v[3] += r0.w;
            v[4] += r1.x; v[5] += r1.y; v[6] += r1.z; v[7] += r1.w;
        }
        if (OUT_RELU) {
#pragma unroll
            for (int j = 0; j < TX; j++) v[j] = fmaxf(v[j], 0.f);
        }
        *(float4*)(out + o)     = make_float4(v[0], v[1], v[2], v[3]);
        *(float4*)(out + o + 4) = make_float4(v[4], v[5], v[6], v[7]);
    }
}

// ---------------------------------------------------------------------------
// Round 12: half-row smem-staged 3x3 s1 p1 conv on 32x32 maps.
// Block = 16 output rows x 32 cols x 4 co (TX=4: 128 threads = 16 rows x 8
// col-groups). Stages 18 padded rows (incl. halo, zero borders) per 4-ci
// chunk -> smem ~10.6KB, grid 2x larger than conv3m.
// blockIdx.x = chunk*2 + rowhalf.
// NCH==1: final output (+bias). NCH>1: partials at
// ((b*NCH + chunk)*COUT + co)*1024 + sp (same layout as conv3m).
// ---------------------------------------------------------------------------
template <int CINC, int CIN_TOTAL, int COUT, int NCH, bool IN_RELU, bool BIAS>
__global__ __launch_bounds__(128)
void conv3h_k(const float* __restrict__ in, const float* __restrict__ wt,
              const float* __restrict__ bs, float* __restrict__ out)
{
    __shared__ float sW[4 * 36];      // current 4 ci: [q][c*9 + tap]
    __shared__ float sI[4 * 648];     // 4 ci x 18 rows x 36 (zero borders)

    const int t     = threadIdx.x;
    const int ox0   = (t & 7) * 4;
    const int oyl   = t >> 3;                 // 0..15
    const int chunk = blockIdx.x >> 1;
    const int rh    = blockIdx.x & 1;
    const int co0   = blockIdx.y * 4;
    const int b     = blockIdx.z;
    const int ci0   = chunk * CINC;
    const int oy    = rh * 16 + oyl;
    const int iyb   = rh * 16 - 1;            // global iy of staged row 0

    float acc[4][4];
#pragma unroll
    for (int c = 0; c < 4; c++) {
        float bv = (NCH == 1 && BIAS) ? __ldg(bs + co0 + c) : 0.f;
#pragma unroll
        for (int j = 0; j < 4; j++) acc[c][j] = bv;
    }

    const float* inb = in + ((size_t)b * CIN_TOTAL + ci0) * 1024;

#pragma unroll 1
    for (int cc = 0; cc < CINC; cc += 4) {
        __syncthreads();
        // stage 4 ci x 18 rows x 9 float4 (xf=8 and OOB rows -> zero)
        for (int i = t; i < 648; i += 128) {
            int q   = i / 162;
            int rem = i - q * 162;
            int r   = rem / 9;
            int xf  = rem - r * 9;
            int iy  = iyb + r;
            float4 v = make_float4(0.f, 0.f, 0.f, 0.f);
            if (xf < 8 && iy >= 0 && iy < 32) {
                v = *(const float4*)(inb + (cc + q) * 1024 + iy * 32 + xf * 4);
                if (IN_RELU) {
                    v.x = fmaxf(v.x, 0.f); v.y = fmaxf(v.y, 0.f);
                    v.z = fmaxf(v.z, 0.f); v.w = fmaxf(v.w, 0.f);
                }
            }
            *(float4*)(sI + q * 648 + r * 36 + xf * 4) = v;
        }
        // stage 4*4*9 = 144 weights (strided, 128 threads)
        for (int i = t; i < 144; i += 128) {
            int q   = i / 36;
            int r   = i - q * 36;
            int c   = r / 9;
            int tap = r - c * 9;
            sW[i] =
                __ldg(wt + ((size_t)(co0 + c) * CIN_TOTAL + ci0 + cc + q) * 9 + tap);
        }
        __syncthreads();

#pragma unroll
        for (int q = 0; q < 4; q++) {
            const float* sw = sW + q * 36;
            const float* si = sI + q * 648;
#pragma unroll
            for (int ky = 0; ky < 3; ky++) {
                const float* row = si + (oyl + ky) * 36;   // halo rows pre-zeroed
                float w[6];
                w[0] = (ox0 > 0) ? row[ox0 - 1] : 0.f;
                float4 v = *(const float4*)(row + ox0);
                w[1] = v.x; w[2] = v.y; w[3] = v.z; w[4] = v.w;
                w[5] = row[ox0 + 4];                       // col 32..35 zero pad
#pragma unroll
                for (int c = 0; c < 4; c++) {
                    float w0 = sw[c * 9 + ky * 3];
                    float w1 = sw[c * 9 + ky * 3 + 1];
                    float w2 = sw[c * 9 + ky * 3 + 2];
#pragma unroll
                    for (int j = 0; j < 4; j++) {
                        acc[c][j] = fmaf(w[j],     w0, acc[c][j]);
                        acc[c][j] = fmaf(w[j + 1], w1, acc[c][j]);
                        acc[c][j] = fmaf(w[j + 2], w2, acc[c][j]);
                    }
                }
            }
        }
    }

#pragma unroll
    for (int c = 0; c < 4; c++) {
        size_t o;
        if (NCH == 1)
            o = (((size_t)b * COUT + (co0 + c)) * 32 + oy) * 32 + ox0;
        else
            o = (((size_t)(b * NCH + chunk) * COUT + (co0 + c)) * 32 + oy) * 32 + ox0;
        *(float4*)(out + o) = make_float4(acc[c][0], acc[c][1], acc[c][2], acc[c][3]);
    }
}

// ---------------------------------------------------------------------------
// Smem-staged k4 s2 p1 conv (e2) (R9, proven).
// ---------------------------------------------------------------------------
template <int CIN, int COUT>
__global__ __launch_bounds__(128)
void conv4m_k(const float* __restrict__ in, const float* __restrict__ wt,
              const float* __restrict__ bs, float* __restrict__ out)
{
    __shared__ float sI[66 * 68];
    __shared__ float sW[64];

    const int t   = threadIdx.x;
    const int ox0 = (t & 3) * 8;
    const int oy  = t >> 2;
    const int co0 = blockIdx.y * 4;
    const int b   = blockIdx.z;
    const int ixb = ox0 * 2 - 1;

    for (int i = t; i < (66 * 68) / 4; i += 128)
        *(float4*)(sI + i * 4) = make_float4(0.f, 0.f, 0.f, 0.f);

    float acc[4][8];
#pragma unroll
    for (int c = 0; c < 4; c++) {
        float bv = __ldg(bs + co0 + c);
#pragma unroll
        for (int j = 0; j < 8; j++) acc[c][j] = bv;
    }

    const float* inb = in + (size_t)b * CIN * 4096;

#pragma unroll 1
    for (int ci = 0; ci < CIN; ci++) {
        __syncthreads();
        const float* ip = inb + ci * 4096;
#pragma unroll
        for (int m = 0; m < 8; m++) {
            int idx = m * 128 + t;
            int y   = idx >> 4;
            int xg  = (idx & 15) * 4;
            float4 v = *(const float4*)(ip + y * 64 + xg);
            *(float4*)(sI + (y + 1) * 68 + xg) = v;
        }
        if (t < 16) {
            int c  = t >> 2;
            int ky = t & 3;
            *(float4*)(sW + t * 4) =
                *(const float4*)(wt + ((size_t)(co0 + c) * CIN + ci) * 16 + ky * 4);
        }
        __syncthreads();

#pragma unroll
        for (int ky = 0; ky < 4; ky++) {
            const float* row = sI + (oy * 2 + ky) * 68;
            float w[18];
            w[0] = (ox0 > 0) ? row[ixb] : 0.f;
#pragma unroll
            for (int m = 0; m < 4; m++) {
                float4 v = *(const float4*)(row + 2 * ox0 + 4 * m);
                w[1 + 4 * m] = v.x; w[2 + 4 * m] = v.y;
                w[3 + 4 * m] = v.z; w[4 + 4 * m] = v.w;
            }
            w[17] = row[ixb + 17];
#pragma unroll
            for (int c = 0; c < 4; c++) {
                float4 wv = *(const float4*)(sW + (c * 4 + ky) * 4);
                float wk[4] = {wv.x, wv.y, wv.z, wv.w};
#pragma unroll
                for (int kx = 0; kx < 4; kx++)
#pragma unroll
                    for (int j = 0; j < 8; j++)
                        acc[c][j] = fmaf(w[j * 2 + kx], wk[kx], acc[c][j]);
            }
        }
    }

#pragma unroll
    for (int c = 0; c < 4; c++) {
        size_t o = (((size_t)b * COUT + (co0 + c)) * 32 + oy) * 32 + ox0;
        float v[8];
#pragma unroll
        for (int j = 0; j < 8; j++) v[j] = fmaxf(acc[c][j], 0.f);
        *(float4*)(out + o)     = make_float4(v[0], v[1], v[2], v[3]);
        *(float4*)(out + o + 4) = make_float4(v[4], v[5], v[6], v[7]);
    }
}

// ---------------------------------------------------------------------------
// Smem-staged ConvTranspose2d(k=4,s=2,p=1) for dt1 (R9, proven).
// ---------------------------------------------------------------------------
template <int CIN, int COUT>
__global__ __launch_bounds__(128)
void dc4m_k(const float* __restrict__ in, const float* __restrict__ wt,
            const float* __restrict__ bs, float* __restrict__ out)
{
    __shared__ float sI[4 * 360];
    __shared__ float sW[4 * 64];

    const int t   = threadIdx.x;
    const int bx  = blockIdx.x;
    const int ox0 = (t & 7) * 8;
    const int oy  = bx * 16 + (t >> 3);
    const int co0 = blockIdx.y * 4;
    const int b   = blockIdx.z;
    const int iy0 = bx * 8 - 1;
    const int ixb = ox0 / 2 - 1;
    const int oyp = oy & 1;

    float acc[4][8];
#pragma unroll
    for (int c = 0; c < 4; c++) {
        float bv = __ldg(bs + co0 + c);
#pragma unroll
        for (int j = 0; j < 8; j++) acc[c][j] = bv;
    }

    const float* inb = in + (size_t)b * CIN * 1024;

#pragma unroll 1
    for (int cc = 0; cc < CIN; cc += 4) {
        __syncthreads();
        for (int i = t; i < 360; i += 128) {
            int q   = i / 90;
            int rem = i - q * 90;
            int r   = rem / 9;
            int xf  = rem - r * 9;
            int iy  = iy0 + r;
            float4 v = make_float4(0.f, 0.f, 0.f, 0.f);
            if (xf < 8 && iy >= 0 && iy < 32) {
                v = *(const float4*)(inb + (cc + q) * 1024 + iy * 32 + xf * 4);
                v.x = fmaxf(v.x, 0.f); v.y = fmaxf(v.y, 0.f);
                v.z = fmaxf(v.z, 0.f); v.w = fmaxf(v.w, 0.f);
            }
            *(float4*)(sI + q * 360 + r * 36 + xf * 4) = v;
        }
        for (int i = t; i < 64; i += 128) {
            int q  = i >> 4;
            int rm = i & 15;
            int c  = rm >> 2;
            int ky = rm & 3;
            *(float4*)(sW + i * 4) =
                *(const float4*)(wt + ((size_t)(co0 + c) * CIN + cc + q) * 16 + ky * 4);
        }
        __syncthreads();

#pragma unroll
        for (int q = 0; q < 4; q++) {
            const float* si = sI + q * 360;
#pragma unroll
            for (int tt = 0; tt < 2; tt++) {
                int ky = oyp + 2 * tt;
                int r  = ((oy - 2 + ky) >> 1) - iy0;
                const float* row = si + r * 36;
                float u[6];
                u[0] = (ixb >= 0) ? row[ixb] : 0.f;
                float4 v = *(const float4*)(row + ixb + 1);
                u[1] = v.x; u[2] = v.y; u[3] = v.z; u[4] = v.w;
                u[5] = row[ixb + 5];
#pragma unroll
                for (int c = 0; c < 4; c++) {
                    float4 wv = *(const float4*)(sW + (q * 16 + c * 4 + ky) * 4);
#pragma unroll
                    for (int j = 0; j < 8; j++) {
                        const int jo = j & 1;
                        const int sh = (j + 1) >> 1;
                        float wl = jo ? wv.y : wv.x;
                        float wh = jo ? wv.w : wv.z;
                        acc[c][j] = fmaf(u[sh],     wl, acc[c][j]);
                        acc[c][j] = fmaf(u[sh + 1], wh, acc[c][j]);
                    }
                }
            }
        }
    }

#pragma unroll
    for (int c = 0; c < 4; c++) {
        size_t o = (((size_t)b * COUT + (co0 + c)) * 64 + oy) * 64 + ox0;
        float v[8];
#pragma unroll
        for (int j = 0; j < 8; j++) v[j] = fmaxf(acc[c][j], 0.f);
        *(float4*)(out + o)     = make_float4(v[0], v[1], v[2], v[3]);
        *(float4*)(out + o + 4) = make_float4(v[4], v[5], v[6], v[7]);
    }
}

// ---------------------------------------------------------------------------
// Smem-staged ConvTranspose2d(k=4,s=2,p=1) for dt2 (R10, proven).
// ---------------------------------------------------------------------------
template <int CIN>
__global__ __launch_bounds__(128)
void dc4m3_k(const float* __restrict__ in, const float* __restrict__ wt,
             const float* __restrict__ bs, float* __restrict__ out)
{
    __shared__ float sI[4 * 408];
    __shared__ float sW[4 * 48];

    const int t   = threadIdx.x;
    const int bx  = blockIdx.x;
    const int ox0 = (t & 15) * 8;
    const int oy  = bx * 8 + (t >> 4);
    const int b   = blockIdx.z;
    const int iy0 = bx * 4 - 1;
    const int ixb = ox0 / 2 - 1;
    const int oyp = oy & 1;

    float acc[3][8];
#pragma unroll
    for (int c = 0; c < 3; c++) {
        float bv = __ldg(bs + c);
#pragma unroll
        for (int j = 0; j < 8; j++) acc[c][j] = bv;
    }

    const float* inb = in + (size_t)b * CIN * 4096;

#pragma unroll 1
    for (int cc = 0; cc < CIN; cc += 4) {
        __syncthreads();
        for (int i = t; i < 408; i += 128) {
            int q   = i / 102;
            int rem = i - q * 102;
            int r   = rem / 17;
            int xf  = rem - r * 17;
            int iy  = iy0 + r;
            float4 v = make_float4(0.f, 0.f, 0.f, 0.f);
            if (xf < 16 && iy >= 0 && iy < 64)
                v = *(const float4*)(inb + (cc + q) * 4096 + iy * 64 + xf * 4);
            *(float4*)(sI + q * 408 + r * 68 + xf * 4) = v;
        }
        for (int i = t; i < 48; i += 128) {
            int q  = i / 12;
            int rm = i - q * 12;
            int c  = rm >> 2;
            int ky = rm & 3;
            *(float4*)(sW + (q * 48 + c * 16 + ky * 4)) =
                *(const float4*)(wt + ((size_t)c * CIN + cc + q) * 16 + ky * 4);
        }
        __syncthreads();

#pragma unroll
        for (int q = 0; q < 4; q++) {
            const float* si = sI + q * 408;
#pragma unroll
            for (int tt = 0; tt < 2; tt++) {
                int ky = oyp + 2 * tt;
                int r  = ((oy - 2 + ky) >> 1) - iy0;
                const float* row = si + r * 68;
                float u[6];
                u[0] = (ixb >= 0) ? row[ixb] : 0.f;
                float4 v = *(const float4*)(row + ixb + 1);
                u[1] = v.x; u[2] = v.y; u[3] = v.z; u[4] = v.w;
                u[5] = row[ixb + 5];
#pragma unroll
                for (int c = 0; c < 3; c++) {
                    float4 wv = *(const float4*)(sW + q * 48 + c * 16 + ky * 4);
#pragma unroll
                    for (int j = 0; j < 8; j++) {
                        const int jo = j & 1;
                        const int sh = (j + 1) >> 1;
                        float wl = jo ? wv.y : wv.x;
                        float wh = jo ? wv.w : wv.z;
                        acc[c][j] = fmaf(u[sh],     wl, acc[c][j]);
                        acc[c][j] = fmaf(u[sh + 1], wh, acc[c][j]);
                    }
                }
            }
        }
    }

#pragma unroll
    for (int c = 0; c < 3; c++) {
        size_t o = (((size_t)b * 3 + c) * 128 + oy) * 128 + ox0;
#pragma unroll
        for (int j = 0; j < 8; j++) out[o + j] = acc[c][j];
    }
}

// ---------------------------------------------------------------------------
// Fused: sum 4 res3x3 partials -> relu -> 1x1 (32->128) -> + residual (R10).
// ---------------------------------------------------------------------------
__global__ __launch_bounds__(128)
void conv1r8_k(const float* __restrict__ part, const float* __restrict__ wt,
               const float* __restrict__ res, float* __restrict__ out)
{
    __shared__ float sW[8 * 32];

    const int t   = threadIdx.x;
    const int ox0 = (t & 3) * 8;
    const int oy  = t >> 2;
    const int co0 = blockIdx.y * 8;
    const int b   = blockIdx.z;

    for (int i = t; i < 256; i += 128)
        sW[i] = __ldg(wt + (co0 + (i >> 5)) * 32 + (i & 31));
    __syncthreads();

    float acc[8][8];
#pragma unroll
    for (int c = 0; c < 8; c++)
#pragma unroll
        for (int j = 0; j < 8; j++) acc[c][j] = 0.f;

    const float* pb = part + (size_t)(b * 4) * 32 * 1024 + oy * 32 + ox0;

#pragma unroll 1
    for (int ci = 0; ci < 32; ci++) {
        const float* p = pb + ci * 1024;
        float w[8] = {0, 0, 0, 0, 0, 0, 0, 0};
#pragma unroll
        for (int ch = 0; ch < 4; ch++) {
            const float* pc = p + ch * 32 * 1024;
            float4 v0 = *(const float4*)pc;
            float4 v1 = *(const float4*)(pc + 4);
            w[0] += v0.x; w[1] += v0.y; w[2] += v0.z; w[3] += v0.w;
            w[4] += v1.x; w[5] += v1.y; w[6] += v1.z; w[7] += v1.w;
        }
#pragma unroll
        for (int m = 0; m < 8; m++) w[m] = fmaxf(w[m], 0.f);
#pragma unroll
        for (int c = 0; c < 8; c++) {
            float wv = sW[c * 32 + ci];
#pragma unroll
            for (int j = 0; j < 8; j++)
                acc[c][j] = fmaf(w[j], wv, acc[c][j]);
        }
    }

#pragma unroll
    for (int c = 0; c < 8; c++) {
        size_t o = (((size_t)b * 128 + (co0 + c)) * 32 + oy) * 32 + ox0;
        float4 r0 = *(const float4*)(res + o);
        float4 r1 = *(const float4*)(res + o + 4);
        *(float4*)(out + o) = make_float4(acc[c][0] + r0.x, acc[c][1] + r0.y,
                                          acc[c][2] + r0.z, acc[c][3] + r0.w);
        *(float4*)(out + o + 4) = make_float4(acc[c][4] + r1.x, acc[c][5] + r1.y,
                                              acc[c][6] + r1.z, acc[c][7] + r1.w);
    }
}

// ---------------------------------------------------------------------------
// VQ (R2, proven)
// ---------------------------------------------------------------------------
__global__ void cnorm_kernel(const float* __restrict__ cb, float* __restrict__ cn)
{
    int k = blockIdx.x * blockDim.x + threadIdx.x;
    if (k >= 512) return;
    const float* c = cb + k * 64;
    float s = 0.f;
#pragma unroll
    for (int d = 0; d < 64; d++) s = fmaf(c[d], c[d], s);
    cn[k] = s;
}

__global__ __launch_bounds__(128)
void vq_kernel(const float* __restrict__ z, const float* __restrict__ cb,
               const float* __restrict__ cn, int* __restrict__ idx,
               float* __restrict__ q, float* __restrict__ err)
{
    int p = blockIdx.x * blockDim.x + threadIdx.x;  // 0..32767
    if (p >= 32768) return;
    int b = p >> 10, s = p & 1023;
    const float* zp = z + (size_t)b * 64 * 1024 + s;
    float zv[64];
#pragma unroll
    for (int d = 0; d < 64; d++) zv[d] = zp[d * 1024];

    float best = 3.4e38f;
    int bk = 0;
#pragma unroll 1
    for (int k = 0; k < 512; k++) {
        const float4* c4 = (const float4*)(cb + (size_t)k * 64);
        float d0 = 0.f, d1 = 0.f, d2 = 0.f, d3 = 0.f;
#pragma unroll
        for (int m = 0; m < 16; m++) {
            float4 cv = __ldg(c4 + m);
            d0 = fmaf(zv[4 * m],     cv.x, d0);
            d1 = fmaf(zv[4 * m + 1], cv.y, d1);
            d2 = fmaf(zv[4 * m + 2], cv.z, d2);
            d3 = fmaf(zv[4 * m + 3], cv.w, d3);
        }
        float dist = __ldg(cn + k) - 2.f * ((d0 + d1) + (d2 + d3));
        if (dist < best) { best = dist; bk = k; }   // strict <: first-min (jnp.argmin)
    }
    idx[p] = bk;
    float* qp = q + (size_t)b * 64 * 1024 + s;
    const float* c = cb + (size_t)bk * 64;
    float e = 0.f;
#pragma unroll
    for (int d = 0; d < 64; d++) {
        float cd = __ldg(c + d);
        qp[d * 1024] = cd;
        float df = zv[d] - cd;
        e = fmaf(df, df, e);
    }
    err[p] = e;
}

__global__ __launch_bounds__(512)
void stats_kernel(const int* __restrict__ idx, const float* __restrict__ err,
                  float* __restrict__ out0, float* __restrict__ outp)
{
    __shared__ int   h[512];
    __shared__ float sm[512];
    int t = threadIdx.x;
    h[t] = 0;
    float s = 0.f;
    __syncthreads();
    for (int i = t; i < 32768; i += 512) {
        atomicAdd(&h[idx[i]], 1);
        s += err[i];
    }
    sm[t] = s;
    __syncthreads();
    for (int off = 256; off > 0; off >>= 1) {
        if (t < off) sm[t] += sm[t + off];
        __syncthreads();
    }
    if (t == 0) out0[0] = 1.25f * sm[0] / 2097152.0f;   // (1+beta)*mse
    __syncthreads();
    float pr = (float)h[t] * (1.0f / 32768.0f);
    sm[t] = pr * logf(pr + 1e-10f);
    __syncthreads();
    for (int off = 256; off > 0; off >>= 1) {
        if (t < off) sm[t] += sm[t + off];
        __syncthreads();
    }
    if (t == 0) outp[0] = expf(-sm[0]);
}

// ---------------------------------------------------------------------------
// Launch
// ---------------------------------------------------------------------------
extern "C" void kernel_launch(void* const* d_in, const int* in_sizes, int n_in,
                              void* d_out, int out_size)
{
    const float* x     = (const float*)d_in[0];
    const float* e_w1  = (const float*)d_in[1];
    const float* e_b1  = (const float*)d_in[2];
    const float* e_w2  = (const float*)d_in[3];
    const float* e_b2  = (const float*)d_in[4];
    const float* e_w3  = (const float*)d_in[5];
    const float* e_b3  = (const float*)d_in[6];
    const float* e_r1a = (const float*)d_in[7];
    const float* e_r1b = (const float*)d_in[8];
    const float* e_r2a = (const float*)d_in[9];
    const float* e_r2b = (const float*)d_in[10];
    const float* pre_w = (const float*)d_in[11];
    const float* pre_b = (const float*)d_in[12];
    const float* cb    = (const float*)d_in[13];
    const float* d_w1  = (const float*)d_in[14];
    const float* d_b1  = (const float*)d_in[15];
    const float* d_r1a = (const float*)d_in[16];
    const float* d_r1b = (const float*)d_in[17];
    const float* d_r2a = (const float*)d_in[18];
    const float* d_r2b = (const float*)d_in[19];
    const float* dt_w1 = (const float*)d_in[20];
    const float* dt_b1 = (const float*)d_in[21];
    const float* dt_w2 = (const float*)d_in[22];
    const float* dt_b2 = (const float*)d_in[23];
    float* out = (float*)d_out;

    float *A, *Bf, *Cc, *Z, *Q, *G, *cn, *err;
    int *idx;
    cudaGetSymbolAddress((void**)&A,    g_A);
    cudaGetSymbolAddress((void**)&Bf,   g_B);
    cudaGetSymbolAddress((void**)&Cc,   g_C);
    cudaGetSymbolAddress((void**)&Z,    g_Z);
    cudaGetSymbolAddress((void**)&Q,    g_Q);
    cudaGetSymbolAddress((void**)&G,    g_G);
    cudaGetSymbolAddress((void**)&cn,   g_cnorm);
    cudaGetSymbolAddress((void**)&err,  g_err);
    cudaGetSymbolAddress((void**)&idx,  g_idx);

    dim3 blk(128);

    // ---- encoder ----
    conv_k<4,4,2,1,4, 3,128,128, 64,64,64, false,true,true,false>
        <<<dim3(4, 16, 32), blk>>>(x, e_w1, e_b1, A, nullptr);
    conv4m_k<64, 128><<<dim3(1, 32, 32), blk>>>(A, e_w2, e_b2, Bf);
    // e3 (half-row): grid.x = 2 row-halves
    conv3h_k<128, 128, 128, 1, false, true>
        <<<dim3(2, 32, 32), blk>>>(Bf, e_w3, e_b3, Cc);
    // encoder res stack (x2): half-row split-4 3x3 -> A partials; fused 1x1
    conv3h_k<32, 128, 32, 4, true, false>
        <<<dim3(8, 8, 32), blk>>>(Cc, e_r1a, nullptr, A);
    conv1r8_k<<<dim3(1, 16, 32), blk>>>(A, e_r1b, Cc, Cc);
    conv3h_k<32, 128, 32, 4, true, false>
        <<<dim3(8, 8, 32), blk>>>(Cc, e_r2a, nullptr, A);
    conv1r8_k<<<dim3(1, 16, 32), blk>>>(A, e_r2b, Cc, Cc);
    conv_k<1,1,1,0,4, 128,32,32, 64,32,32, true,false,true,false>
        <<<dim3(1, 16, 32), blk>>>(Cc, pre_w, pre_b, Z, nullptr);

    // ---- vector quantizer ----
    cnorm_kernel<<<2, 256>>>(cb, cn);
    vq_kernel<<<256, 128>>>(Z, cb, cn, idx, Q, err);
    stats_kernel<<<1, 512>>>(idx, err, out, out + (out_size - 1));

    // ---- decoder ----
    conv3h_k<64, 64, 128, 1, false, true>
        <<<dim3(2, 32, 32), blk>>>(Q, d_w1, d_b1, G);
    conv3h_k<32, 128, 32, 4, true, false>
        <<<dim3(8, 8, 32), blk>>>(G, d_r1a, nullptr, A);
    conv1r8_k<<<dim3(1, 16, 32), blk>>>(A, d_r1b, G, G);
    conv3h_k<32, 128, 32, 4, true, false>
        <<<dim3(8, 8, 32), blk>>>(G, d_r2a, nullptr, A);
    conv1r8_k<<<dim3(1, 16, 32), blk>>>(A, d_r2b, G, G);
    dc4m_k<128, 64><<<dim3(4, 16, 32), blk>>>(G, dt_w1, dt_b1, A);
    dc4m3_k<64><<<dim3(16, 1, 32), blk>>>(A, dt_w2, dt_b2, out + 1);
}

// round 13
// speedup vs baseline: 1.1166x; 1.1166x over previous
#include <cuda_runtime.h>
#include <math.h>

// ---------------------------------------------------------------------------
// VQ-VAE forward, fp32. Round 13: revert to R11 (conv3h regression undone);
// single change: e3 split-2 over ci (conv3m NCH=2 partials + comb_k).
// Output layout: [loss, x_recon(1572864), perplexity]
// ---------------------------------------------------------------------------

// Scratch (device globals; no allocation allowed)
__device__ float g_A[32u * 64 * 64 * 64];    // e1 out / dt1 out / partials
__device__ float g_B[32u * 128 * 32 * 32];   // e2 out
__device__ float g_C[32u * 128 * 32 * 32];   // e3 out + encoder res stack
__device__ float g_Z[32u * 64 * 32 * 32];    // pre-VQ z
__device__ float g_Q[32u * 64 * 32 * 32];    // quantized q
__device__ float g_G[32u * 128 * 32 * 32];   // decoder stack
__device__ int   g_idx[32768];
__device__ float g_cnorm[512];
__device__ float g_err[32768];

// ---------------------------------------------------------------------------
// Generic direct conv (R2, proven): used for e1 (k4s2) and pre (1x1).
// ---------------------------------------------------------------------------
template <int KH, int KW, int S, int P, int TCO,
          int CIN, int HIN, int WIN, int COUT, int HOUT, int WOUT,
          bool IN_RELU, bool OUT_RELU, bool BIAS, bool ADD>
__global__ __launch_bounds__(128)
void conv_k(const float* __restrict__ in, const float* __restrict__ wt,
            const float* __restrict__ bs, float* __restrict__ out,
            const float* __restrict__ res)
{
    constexpr int TX   = 8;
    constexpr int WINW = (TX - 1) * S + KW;
    static_assert((HOUT * WOUT / TX) % 128 == 0, "tiles fill blocks");

    int tid = blockIdx.x * 128 + threadIdx.x;
    int ox0 = (tid * TX) % WOUT;
    int oy  = (tid * TX) / WOUT;
    int co0 = blockIdx.y * TCO;
    int b   = blockIdx.z;

    float acc[TCO][TX];
#pragma unroll
    for (int c = 0; c < TCO; c++) {
        float bv = BIAS ? __ldg(bs + co0 + c) : 0.f;
#pragma unroll
        for (int j = 0; j < TX; j++) acc[c][j] = bv;
    }

    const float* inb = in + (size_t)b * CIN * HIN * WIN;
    const int ixb = ox0 * S - P;

#pragma unroll 1
    for (int ci = 0; ci < CIN; ci++) {
        const float* ip  = inb + ci * HIN * WIN;
        const float* wci = wt + ((size_t)co0 * CIN + ci) * KH * KW;
#pragma unroll
        for (int ky = 0; ky < KH; ky++) {
            int iy = oy * S - P + ky;
            if (P > 0 && (iy < 0 || iy >= HIN)) continue;
            const float* row = ip + iy * WIN;
            float w[WINW];
            if constexpr (P == 0) {
                float4 v0 = *(const float4*)(row + ox0);
                float4 v1 = *(const float4*)(row + ox0 + 4);
                w[0] = v0.x; w[1] = v0.y; w[2] = v0.z; w[3] = v0.w;
                w[4] = v1.x; w[5] = v1.y; w[6] = v1.z; w[7] = v1.w;
            } else {
                w[0] = (ixb >= 0) ? row[ixb] : 0.f;
#pragma unroll
                for (int m = 0; m < (WINW - 2) / 4; m++) {
                    float4 v = *(const float4*)(row + ixb + 1 + 4 * m);
                    w[1 + 4 * m] = v.x; w[2 + 4 * m] = v.y;
                    w[3 + 4 * m] = v.z; w[4 + 4 * m] = v.w;
                }
                w[WINW - 1] = (ixb + WINW - 1 < WIN) ? row[ixb + WINW - 1] : 0.f;
            }
            if (IN_RELU) {
#pragma unroll
                for (int m = 0; m < WINW; m++) w[m] = fmaxf(w[m], 0.f);
            }
#pragma unroll
            for (int c = 0; c < TCO; c++) {
                const float* wp = wci + c * CIN * KH * KW + ky * KW;
                if constexpr (KW == 4) {
                    float4 wv = *(const float4*)wp;
                    float wk[4] = {wv.x, wv.y, wv.z, wv.w};
#pragma unroll
                    for (int kx = 0; kx < 4; kx++)
#pragma unroll
                        for (int j = 0; j < TX; j++)
                            acc[c][j] = fmaf(w[j * S + kx], wk[kx], acc[c][j]);
                } else {
#pragma unroll
                    for (int kx = 0; kx < KW; kx++) {
                        float wv = __ldg(wp + kx);
#pragma unroll
                        for (int j = 0; j < TX; j++)
                            acc[c][j] = fmaf(w[j * S + kx], wv, acc[c][j]);
                    }
                }
            }
        }
    }

#pragma unroll
    for (int c = 0; c < TCO; c++) {
        size_t o = (((size_t)b * COUT + (co0 + c)) * HOUT + oy) * WOUT + ox0;
        float v[TX];
#pragma unroll
        for (int j = 0; j < TX; j++) v[j] = acc[c][j];
        if (ADD) {
            float4 r0 = *(const float4*)(res + o);
            float4 r1 = *(const float4*)(res + o + 4);
            v[0] += r0.x; v[1] += r0.y; v[2] += r0.z; v[3] += r0.w;
            v[4] += r1.x; v[5] += r1.y; v[6] += r1.z; v[7] += r1.w;
        }
        if (OUT_RELU) {
#pragma unroll
            for (int j = 0; j < TX; j++) v[j] = fmaxf(v[j], 0.f);
        }
        *(float4*)(out + o)     = make_float4(v[0], v[1], v[2], v[3]);
        *(float4*)(out + o + 4) = make_float4(v[4], v[5], v[6], v[7]);
    }
}

// ---------------------------------------------------------------------------
// Smem-staged 3x3 s1 p1 conv on 32x32 maps (R8, proven).
// NCH==1: final output (+bias). NCH>1: partials at
// ((b*NCH + chunk)*COUT + co)*1024 + sp.
// ---------------------------------------------------------------------------
template <int CINC, int CIN_TOTAL, int COUT, int NCH, bool IN_RELU, bool BIAS>
__global__ __launch_bounds__(128)
void conv3m_k(const float* __restrict__ in, const float* __restrict__ wt,
              const float* __restrict__ bs, float* __restrict__ out)
{
    __shared__ float sW[4 * 36];          // current 4 ci: [q][c*9 + tap]
    __shared__ float sI[4 * 36 * 32];     // 4 channels, rows padded to 36

    const int t     = threadIdx.x;
    const int ox0   = (t & 3) * 8;
    const int oy    = t >> 2;
    const int chunk = blockIdx.x;
    const int co0   = blockIdx.y * 4;
    const int b     = blockIdx.z;
    const int ci0   = chunk * CINC;

    float acc[4][8];
#pragma unroll
    for (int c = 0; c < 4; c++) {
        float bv = (NCH == 1 && BIAS) ? __ldg(bs + co0 + c) : 0.f;
#pragma unroll
        for (int j = 0; j < 8; j++) acc[c][j] = bv;
    }

    const float* inb = in + ((size_t)b * CIN_TOTAL + ci0) * 1024;

#pragma unroll 1
    for (int cc = 0; cc < CINC; cc += 4) {
        __syncthreads();
#pragma unroll
        for (int m = 0; m < 8; m++) {
            int idx = m * 128 + t;
            int q   = idx >> 8;
            int rem = idx & 255;
            int y   = rem >> 3;
            int xg  = (rem & 7) * 4;
            float4 v = *(const float4*)(inb + (cc + q) * 1024 + y * 32 + xg);
            if (IN_RELU) {
                v.x = fmaxf(v.x, 0.f); v.y = fmaxf(v.y, 0.f);
                v.z = fmaxf(v.z, 0.f); v.w = fmaxf(v.w, 0.f);
            }
            *(float4*)(sI + q * 1152 + y * 36 + xg) = v;
        }
        for (int i = t; i < 144; i += 128) {
            int q   = i / 36;
            int r   = i - q * 36;
            int c   = r / 9;
            int tap = r - c * 9;
            sW[i] =
                __ldg(wt + ((size_t)(co0 + c) * CIN_TOTAL + ci0 + cc + q) * 9 + tap);
        }
        __syncthreads();

#pragma unroll
        for (int q = 0; q < 4; q++) {
            const float* sw = sW + q * 36;
            const float* si = sI + q * 1152;
#pragma unroll
            for (int ky = 0; ky < 3; ky++) {
                int iy = oy - 1 + ky;
                if (iy < 0 || iy >= 32) continue;
                const float* row = si + iy * 36;
                float w[10];
                w[0] = (ox0 > 0) ? row[ox0 - 1] : 0.f;
                float4 v0 = *(const float4*)(row + ox0);
                float4 v1 = *(const float4*)(row + ox0 + 4);
                w[1] = v0.x; w[2] = v0.y; w[3] = v0.z; w[4] = v0.w;
                w[5] = v1.x; w[6] = v1.y; w[7] = v1.z; w[8] = v1.w;
                w[9] = (ox0 < 24) ? row[ox0 + 8] : 0.f;
#pragma unroll
                for (int c = 0; c < 4; c++) {
                    float w0 = sw[c * 9 + ky * 3];
                    float w1 = sw[c * 9 + ky * 3 + 1];
                    float w2 = sw[c * 9 + ky * 3 + 2];
#pragma unroll
                    for (int j = 0; j < 8; j++) {
                        acc[c][j] = fmaf(w[j],     w0, acc[c][j]);
                        acc[c][j] = fmaf(w[j + 1], w1, acc[c][j]);
                        acc[c][j] = fmaf(w[j + 2], w2, acc[c][j]);
                    }
                }
            }
        }
    }

#pragma unroll
    for (int c = 0; c < 4; c++) {
        size_t o;
        if (NCH == 1)
            o = (((size_t)b * COUT + (co0 + c)) * 32 + oy) * 32 + ox0;
        else
            o = (((size_t)(b * NCH + chunk) * COUT + (co0 + c)) * 32 + oy) * 32 + ox0;
        *(float4*)(out + o)     = make_float4(acc[c][0], acc[c][1], acc[c][2], acc[c][3]);
        *(float4*)(out + o + 4) = make_float4(acc[c][4], acc[c][5], acc[c][6], acc[c][7]);
    }
}

// ---------------------------------------------------------------------------
// Combine 2 partials (+bias, optional relu) (R5, proven).
// src index = dst index + b*bstr per buffer.
// ---------------------------------------------------------------------------
template <int COUT, bool RELU>
__global__ __launch_bounds__(256)
void comb_k(const float* __restrict__ p0, const float* __restrict__ p1,
            const float* __restrict__ bs, float* __restrict__ dst, int bstr)
{
    int i4 = blockIdx.x * 256 + threadIdx.x;
    if (i4 >= 32 * COUT * 256) return;
    size_t i = (size_t)i4 * 4;
    int b  = i4 >> 8;
    int co = b % COUT;
    b = b / COUT;
    size_t s = i + (size_t)b * bstr;
    float4 a0 = *(const float4*)(p0 + s);
    float4 a1 = *(const float4*)(p1 + s);
    float bv = __ldg(bs + co);
    float v0 = a0.x + a1.x + bv, v1 = a0.y + a1.y + bv;
    float v2 = a0.z + a1.z + bv, v3 = a0.w + a1.w + bv;
    if (RELU) {
        v0 = fmaxf(v0, 0.f); v1 = fmaxf(v1, 0.f);
        v2 = fmaxf(v2, 0.f); v3 = fmaxf(v3, 0.f);
    }
    *(float4*)(dst + i) = make_float4(v0, v1, v2, v3);
}

// ---------------------------------------------------------------------------
// Smem-staged k4 s2 p1 conv (e2) (R9, proven).
// ---------------------------------------------------------------------------
template <int CIN, int COUT>
__global__ __launch_bounds__(128)
void conv4m_k(const float* __restrict__ in, const float* __restrict__ wt,
              const float* __restrict__ bs, float* __restrict__ out)
{
    __shared__ float sI[66 * 68];
    __shared__ float sW[64];

    const int t   = threadIdx.x;
    const int ox0 = (t & 3) * 8;
    const int oy  = t >> 2;
    const int co0 = blockIdx.y * 4;
    const int b   = blockIdx.z;
    const int ixb = ox0 * 2 - 1;

    for (int i = t; i < (66 * 68) / 4; i += 128)
        *(float4*)(sI + i * 4) = make_float4(0.f, 0.f, 0.f, 0.f);

    float acc[4][8];
#pragma unroll
    for (int c = 0; c < 4; c++) {
        float bv = __ldg(bs + co0 + c);
#pragma unroll
        for (int j = 0; j < 8; j++) acc[c][j] = bv;
    }

    const float* inb = in + (size_t)b * CIN * 4096;

#pragma unroll 1
    for (int ci = 0; ci < CIN; ci++) {
        __syncthreads();
        const float* ip = inb + ci * 4096;
#pragma unroll
        for (int m = 0; m < 8; m++) {
            int idx = m * 128 + t;
            int y   = idx >> 4;
            int xg  = (idx & 15) * 4;
            float4 v = *(const float4*)(ip + y * 64 + xg);
            *(float4*)(sI + (y + 1) * 68 + xg) = v;
        }
        if (t < 16) {
            int c  = t >> 2;
            int ky = t & 3;
            *(float4*)(sW + t * 4) =
                *(const float4*)(wt + ((size_t)(co0 + c) * CIN + ci) * 16 + ky * 4);
        }
        __syncthreads();

#pragma unroll
        for (int ky = 0; ky < 4; ky++) {
            const float* row = sI + (oy * 2 + ky) * 68;
            float w[18];
            w[0] = (ox0 > 0) ? row[ixb] : 0.f;
#pragma unroll
            for (int m = 0; m < 4; m++) {
                float4 v = *(const float4*)(row + 2 * ox0 + 4 * m);
                w[1 + 4 * m] = v.x; w[2 + 4 * m] = v.y;
                w[3 + 4 * m] = v.z; w[4 + 4 * m] = v.w;
            }
            w[17] = row[ixb + 17];
#pragma unroll
            for (int c = 0; c < 4; c++) {
                float4 wv = *(const float4*)(sW + (c * 4 + ky) * 4);
                float wk[4] = {wv.x, wv.y, wv.z, wv.w};
#pragma unroll
                for (int kx = 0; kx < 4; kx++)
#pragma unroll
                    for (int j = 0; j < 8; j++)
                        acc[c][j] = fmaf(w[j * 2 + kx], wk[kx], acc[c][j]);
            }
        }
    }

#pragma unroll
    for (int c = 0; c < 4; c++) {
        size_t o = (((size_t)b * COUT + (co0 + c)) * 32 + oy) * 32 + ox0;
        float v[8];
#pragma unroll
        for (int j = 0; j < 8; j++) v[j] = fmaxf(acc[c][j], 0.f);
        *(float4*)(out + o)     = make_float4(v[0], v[1], v[2], v[3]);
        *(float4*)(out + o + 4) = make_float4(v[4], v[5], v[6], v[7]);
    }
}

// ---------------------------------------------------------------------------
// Smem-staged ConvTranspose2d(k=4,s=2,p=1) for dt1 (R9, proven).
// ---------------------------------------------------------------------------
template <int CIN, int COUT>
__global__ __launch_bounds__(128)
void dc4m_k(const float* __restrict__ in, const float* __restrict__ wt,
            const float* __restrict__ bs, float* __restrict__ out)
{
    __shared__ float sI[4 * 360];
    __shared__ float sW[4 * 64];

    const int t   = threadIdx.x;
    const int bx  = blockIdx.x;
    const int ox0 = (t & 7) * 8;
    const int oy  = bx * 16 + (t >> 3);
    const int co0 = blockIdx.y * 4;
    const int b   = blockIdx.z;
    const int iy0 = bx * 8 - 1;
    const int ixb = ox0 / 2 - 1;
    const int oyp = oy & 1;

    float acc[4][8];
#pragma unroll
    for (int c = 0; c < 4; c++) {
        float bv = __ldg(bs + co0 + c);
#pragma unroll
        for (int j = 0; j < 8; j++) acc[c][j] = bv;
    }

    const float* inb = in + (size_t)b * CIN * 1024;

#pragma unroll 1
    for (int cc = 0; cc < CIN; cc += 4) {
        __syncthreads();
        for (int i = t; i < 360; i += 128) {
            int q   = i / 90;
            int rem = i - q * 90;
            int r   = rem / 9;
            int xf  = rem - r * 9;
            int iy  = iy0 + r;
            float4 v = make_float4(0.f, 0.f, 0.f, 0.f);
            if (xf < 8 && iy >= 0 && iy < 32) {
                v = *(const float4*)(inb + (cc + q) * 1024 + iy * 32 + xf * 4);
                v.x = fmaxf(v.x, 0.f); v.y = fmaxf(v.y, 0.f);
                v.z = fmaxf(v.z, 0.f); v.w = fmaxf(v.w, 0.f);
            }
            *(float4*)(sI + q * 360 + r * 36 + xf * 4) = v;
        }
        for (int i = t; i < 64; i += 128) {
            int q  = i >> 4;
            int rm = i & 15;
            int c  = rm >> 2;
            int ky = rm & 3;
            *(float4*)(sW + i * 4) =
                *(const float4*)(wt + ((size_t)(co0 + c) * CIN + cc + q) * 16 + ky * 4);
        }
        __syncthreads();

#pragma unroll
        for (int q = 0; q < 4; q++) {
            const float* si = sI + q * 360;
#pragma unroll
            for (int tt = 0; tt < 2; tt++) {
                int ky = oyp + 2 * tt;
                int r  = ((oy - 2 + ky) >> 1) - iy0;
                const float* row = si + r * 36;
                float u[6];
                u[0] = (ixb >= 0) ? row[ixb] : 0.f;
                float4 v = *(const float4*)(row + ixb + 1);
                u[1] = v.x; u[2] = v.y; u[3] = v.z; u[4] = v.w;
                u[5] = row[ixb + 5];
#pragma unroll
                for (int c = 0; c < 4; c++) {
                    float4 wv = *(const float4*)(sW + (q * 16 + c * 4 + ky) * 4);
#pragma unroll
                    for (int j = 0; j < 8; j++) {
                        const int jo = j & 1;
                        const int sh = (j + 1) >> 1;
                        float wl = jo ? wv.y : wv.x;
                        float wh = jo ? wv.w : wv.z;
                        acc[c][j] = fmaf(u[sh],     wl, acc[c][j]);
                        acc[c][j] = fmaf(u[sh + 1], wh, acc[c][j]);
                    }
                }
            }
        }
    }

#pragma unroll
    for (int c = 0; c < 4; c++) {
        size_t o = (((size_t)b * COUT + (co0 + c)) * 64 + oy) * 64 + ox0;
        float v[8];
#pragma unroll
        for (int j = 0; j < 8; j++) v[j] = fmaxf(acc[c][j], 0.f);
        *(float4*)(out + o)     = make_float4(v[0], v[1], v[2], v[3]);
        *(float4*)(out + o + 4) = make_float4(v[4], v[5], v[6], v[7]);
    }
}

// ---------------------------------------------------------------------------
// Smem-staged ConvTranspose2d(k=4,s=2,p=1) for dt2 (R10, proven).
// ---------------------------------------------------------------------------
template <int CIN>
__global__ __launch_bounds__(128)
void dc4m3_k(const float* __restrict__ in, const float* __restrict__ wt,
             const float* __restrict__ bs, float* __restrict__ out)
{
    __shared__ float sI[4 * 408];
    __shared__ float sW[4 * 48];

    const int t   = threadIdx.x;
    const int bx  = blockIdx.x;
    const int ox0 = (t & 15) * 8;
    const int oy  = bx * 8 + (t >> 4);
    const int b   = blockIdx.z;
    const int iy0 = bx * 4 - 1;
    const int ixb = ox0 / 2 - 1;
    const int oyp = oy & 1;

    float acc[3][8];
#pragma unroll
    for (int c = 0; c < 3; c++) {
        float bv = __ldg(bs + c);
#pragma unroll
        for (int j = 0; j < 8; j++) acc[c][j] = bv;
    }

    const float* inb = in + (size_t)b * CIN * 4096;

#pragma unroll 1
    for (int cc = 0; cc < CIN; cc += 4) {
        __syncthreads();
        for (int i = t; i < 408; i += 128) {
            int q   = i / 102;
            int rem = i - q * 102;
            int r   = rem / 17;
            int xf  = rem - r * 17;
            int iy  = iy0 + r;
            float4 v = make_float4(0.f, 0.f, 0.f, 0.f);
            if (xf < 16 && iy >= 0 && iy < 64)
                v = *(const float4*)(inb + (cc + q) * 4096 + iy * 64 + xf * 4);
            *(float4*)(sI + q * 408 + r * 68 + xf * 4) = v;
        }
        for (int i = t; i < 48; i += 128) {
            int q  = i / 12;
            int rm = i - q * 12;
            int c  = rm >> 2;
            int ky = rm & 3;
            *(float4*)(sW + (q * 48 + c * 16 + ky * 4)) =
                *(const float4*)(wt + ((size_t)c * CIN + cc + q) * 16 + ky * 4);
        }
        __syncthreads();

#pragma unroll
        for (int q = 0; q < 4; q++) {
            const float* si = sI + q * 408;
#pragma unroll
            for (int tt = 0; tt < 2; tt++) {
                int ky = oyp + 2 * tt;
                int r  = ((oy - 2 + ky) >> 1) - iy0;
                const float* row = si + r * 68;
                float u[6];
                u[0] = (ixb >= 0) ? row[ixb] : 0.f;
                float4 v = *(const float4*)(row + ixb + 1);
                u[1] = v.x; u[2] = v.y; u[3] = v.z; u[4] = v.w;
                u[5] = row[ixb + 5];
#pragma unroll
                for (int c = 0; c < 3; c++) {
                    float4 wv = *(const float4*)(sW + q * 48 + c * 16 + ky * 4);
#pragma unroll
                    for (int j = 0; j < 8; j++) {
                        const int jo = j & 1;
                        const int sh = (j + 1) >> 1;
                        float wl = jo ? wv.y : wv.x;
                        float wh = jo ? wv.w : wv.z;
                        acc[c][j] = fmaf(u[sh],     wl, acc[c][j]);
                        acc[c][j] = fmaf(u[sh + 1], wh, acc[c][j]);
                    }
                }
            }
        }
    }

#pragma unroll
    for (int c = 0; c < 3; c++) {
        size_t o = (((size_t)b * 3 + c) * 128 + oy) * 128 + ox0;
#pragma unroll
        for (int j = 0; j < 8; j++) out[o + j] = acc[c][j];
    }
}

// ---------------------------------------------------------------------------
// Fused: sum 4 res3x3 partials -> relu -> 1x1 (32->128) -> + residual (R10).
// ---------------------------------------------------------------------------
__global__ __launch_bounds__(128)
void conv1r8_k(const float* __restrict__ part, const float* __restrict__ wt,
               const float* __restrict__ res, float* __restrict__ out)
{
    __shared__ float sW[8 * 32];

    const int t   = threadIdx.x;
    const int ox0 = (t & 3) * 8;
    const int oy  = t >> 2;
    const int co0 = blockIdx.y * 8;
    const int b   = blockIdx.z;

    for (int i = t; i < 256; i += 128)
        sW[i] = __ldg(wt + (co0 + (i >> 5)) * 32 + (i & 31));
    __syncthreads();

    float acc[8][8];
#pragma unroll
    for (int c = 0; c < 8; c++)
#pragma unroll
        for (int j = 0; j < 8; j++) acc[c][j] = 0.f;

    const float* pb = part + (size_t)(b * 4) * 32 * 1024 + oy * 32 + ox0;

#pragma unroll 1
    for (int ci = 0; ci < 32; ci++) {
        const float* p = pb + ci * 1024;
        float w[8] = {0, 0, 0, 0, 0, 0, 0, 0};
#pragma unroll
        for (int ch = 0; ch < 4; ch++) {
            const float* pc = p + ch * 32 * 1024;
            float4 v0 = *(const float4*)pc;
            float4 v1 = *(const float4*)(pc + 4);
            w[0] += v0.x; w[1] += v0.y; w[2] += v0.z; w[3] += v0.w;
            w[4] += v1.x; w[5] += v1.y; w[6] += v1.z; w[7] += v1.w;
        }
#pragma unroll
        for (int m = 0; m < 8; m++) w[m] = fmaxf(w[m], 0.f);
#pragma unroll
        for (int c = 0; c < 8; c++) {
            float wv = sW[c * 32 + ci];
#pragma unroll
            for (int j = 0; j < 8; j++)
                acc[c][j] = fmaf(w[j], wv, acc[c][j]);
        }
    }

#pragma unroll
    for (int c = 0; c < 8; c++) {
        size_t o = (((size_t)b * 128 + (co0 + c)) * 32 + oy) * 32 + ox0;
        float4 r0 = *(const float4*)(res + o);
        float4 r1 = *(const float4*)(res + o + 4);
        *(float4*)(out + o) = make_float4(acc[c][0] + r0.x, acc[c][1] + r0.y,
                                          acc[c][2] + r0.z, acc[c][3] + r0.w);
        *(float4*)(out + o + 4) = make_float4(acc[c][4] + r1.x, acc[c][5] + r1.y,
                                              acc[c][6] + r1.z, acc[c][7] + r1.w);
    }
}

// ---------------------------------------------------------------------------
// VQ (R2, proven)
// ---------------------------------------------------------------------------
__global__ void cnorm_kernel(const float* __restrict__ cb, float* __restrict__ cn)
{
    int k = blockIdx.x * blockDim.x + threadIdx.x;
    if (k >= 512) return;
    const float* c = cb + k * 64;
    float s = 0.f;
#pragma unroll
    for (int d = 0; d < 64; d++) s = fmaf(c[d], c[d], s);
    cn[k] = s;
}

__global__ __launch_bounds__(128)
void vq_kernel(const float* __restrict__ z, const float* __restrict__ cb,
               const float* __restrict__ cn, int* __restrict__ idx,
               float* __restrict__ q, float* __restrict__ err)
{
    int p = blockIdx.x * blockDim.x + threadIdx.x;  // 0..32767
    if (p >= 32768) return;
    int b = p >> 10, s = p & 1023;
    const float* zp = z + (size_t)b * 64 * 1024 + s;
    float zv[64];
#pragma unroll
    for (int d = 0; d < 64; d++) zv[d] = zp[d * 1024];

    float best = 3.4e38f;
    int bk = 0;
#pragma unroll 1
    for (int k = 0; k < 512; k++) {
        const float4* c4 = (const float4*)(cb + (size_t)k * 64);
        float d0 = 0.f, d1 = 0.f, d2 = 0.f, d3 = 0.f;
#pragma unroll
        for (int m = 0; m < 16; m++) {
            float4 cv = __ldg(c4 + m);
            d0 = fmaf(zv[4 * m],     cv.x, d0);
            d1 = fmaf(zv[4 * m + 1], cv.y, d1);
            d2 = fmaf(zv[4 * m + 2], cv.z, d2);
            d3 = fmaf(zv[4 * m + 3], cv.w, d3);
        }
        float dist = __ldg(cn + k) - 2.f * ((d0 + d1) + (d2 + d3));
        if (dist < best) { best = dist; bk = k; }   // strict <: first-min (jnp.argmin)
    }
    idx[p] = bk;
    float* qp = q + (size_t)b * 64 * 1024 + s;
    const float* c = cb + (size_t)bk * 64;
    float e = 0.f;
#pragma unroll
    for (int d = 0; d < 64; d++) {
        float cd = __ldg(c + d);
        qp[d * 1024] = cd;
        float df = zv[d] - cd;
        e = fmaf(df, df, e);
    }
    err[p] = e;
}

__global__ __launch_bounds__(512)
void stats_kernel(const int* __restrict__ idx, const float* __restrict__ err,
                  float* __restrict__ out0, float* __restrict__ outp)
{
    __shared__ int   h[512];
    __shared__ float sm[512];
    int t = threadIdx.x;
    h[t] = 0;
    float s = 0.f;
    __syncthreads();
    for (int i = t; i < 32768; i += 512) {
        atomicAdd(&h[idx[i]], 1);
        s += err[i];
    }
    sm[t] = s;
    __syncthreads();
    for (int off = 256; off > 0; off >>= 1) {
        if (t < off) sm[t] += sm[t + off];
        __syncthreads();
    }
    if (t == 0) out0[0] = 1.25f * sm[0] / 2097152.0f;   // (1+beta)*mse
    __syncthreads();
    float pr = (float)h[t] * (1.0f / 32768.0f);
    sm[t] = pr * logf(pr + 1e-10f);
    __syncthreads();
    for (int off = 256; off > 0; off >>= 1) {
        if (t < off) sm[t] += sm[t + off];
        __syncthreads();
    }
    if (t == 0) outp[0] = expf(-sm[0]);
}

// ---------------------------------------------------------------------------
// Launch
// ---------------------------------------------------------------------------
extern "C" void kernel_launch(void* const* d_in, const int* in_sizes, int n_in,
                              void* d_out, int out_size)
{
    const float* x     = (const float*)d_in[0];
    const float* e_w1  = (const float*)d_in[1];
    const float* e_b1  = (const float*)d_in[2];
    const float* e_w2  = (const float*)d_in[3];
    const float* e_b2  = (const float*)d_in[4];
    const float* e_w3  = (const float*)d_in[5];
    const float* e_b3  = (const float*)d_in[6];
    const float* e_r1a = (const float*)d_in[7];
    const float* e_r1b = (const float*)d_in[8];
    const float* e_r2a = (const float*)d_in[9];
    const float* e_r2b = (const float*)d_in[10];
    const float* pre_w = (const float*)d_in[11];
    const float* pre_b = (const float*)d_in[12];
    const float* cb    = (const float*)d_in[13];
    const float* d_w1  = (const float*)d_in[14];
    const float* d_b1  = (const float*)d_in[15];
    const float* d_r1a = (const float*)d_in[16];
    const float* d_r1b = (const float*)d_in[17];
    const float* d_r2a = (const float*)d_in[18];
    const float* d_r2b = (const float*)d_in[19];
    const float* dt_w1 = (const float*)d_in[20];
    const float* dt_b1 = (const float*)d_in[21];
    const float* dt_w2 = (const float*)d_in[22];
    const float* dt_b2 = (const float*)d_in[23];
    float* out = (float*)d_out;

    float *A, *Bf, *Cc, *Z, *Q, *G, *cn, *err;
    int *idx;
    cudaGetSymbolAddress((void**)&A,    g_A);
    cudaGetSymbolAddress((void**)&Bf,   g_B);
    cudaGetSymbolAddress((void**)&Cc,   g_C);
    cudaGetSymbolAddress((void**)&Z,    g_Z);
    cudaGetSymbolAddress((void**)&Q,    g_Q);
    cudaGetSymbolAddress((void**)&G,    g_G);
    cudaGetSymbolAddress((void**)&cn,   g_cnorm);
    cudaGetSymbolAddress((void**)&err,  g_err);
    cudaGetSymbolAddress((void**)&idx,  g_idx);

    dim3 blk(128);
    const int CB128 = 32 * 128 * 256;   // float4 count for COUT=128 combine

    // ---- encoder ----
    conv_k<4,4,2,1,4, 3,128,128, 64,64,64, false,true,true,false>
        <<<dim3(4, 16, 32), blk>>>(x, e_w1, e_b1, A, nullptr);
    conv4m_k<64, 128><<<dim3(1, 32, 32), blk>>>(A, e_w2, e_b2, Bf);
    // e3 split-2 over ci: partials in A; combine -> Cc (bias, no relu)
    conv3m_k<64, 128, 128, 2, false, false>
        <<<dim3(2, 32, 32), blk>>>(Bf, e_w3, nullptr, A);
    comb_k<128, false><<<(CB128 + 255) / 256, 256>>>(A, A + 128 * 1024, e_b3, Cc,
                                                     128 * 1024);
    // encoder res stack (x2): split-4 3x3 -> A partials; fused 1x1+residual
    conv3m_k<32, 128, 32, 4, true, false>
        <<<dim3(4, 8, 32), blk>>>(Cc, e_r1a, nullptr, A);
    conv1r8_k<<<dim3(1, 16, 32), blk>>>(A, e_r1b, Cc, Cc);
    conv3m_k<32, 128, 32, 4, true, false>
        <<<dim3(4, 8, 32), blk>>>(Cc, e_r2a, nullptr, A);
    conv1r8_k<<<dim3(1, 16, 32), blk>>>(A, e_r2b, Cc, Cc);
    conv_k<1,1,1,0,4, 128,32,32, 64,32,32, true,false,true,false>
        <<<dim3(1, 16, 32), blk>>>(Cc, pre_w, pre_b, Z, nullptr);

    // ---- vector quantizer ----
    cnorm_kernel<<<2, 256>>>(cb, cn);
    vq_kernel<<<256, 128>>>(Z, cb, cn, idx, Q, err);
    stats_kernel<<<1, 512>>>(idx, err, out, out + (out_size - 1));

    // ---- decoder ----
    conv3m_k<64, 64, 128, 1, false, true>
        <<<dim3(1, 32, 32), blk>>>(Q, d_w1, d_b1, G);
    conv3m_k<32, 128, 32, 4, true, false>
        <<<dim3(4, 8, 32), blk>>>(G, d_r1a, nullptr, A);
    conv1r8_k<<<dim3(1, 16, 32), blk>>>(A, d_r1b, G, G);
    conv3m_k<32, 128, 32, 4, true, false>
        <<<dim3(4, 8, 32), blk>>>(G, d_r2a, nullptr, A);
    conv1r8_k<<<dim3(1, 16, 32), blk>>>(A, d_r2b, G, G);
    dc4m_k<128, 64><<<dim3(4, 16, 32), blk>>>(G, dt_w1, dt_b1, A);
    dc4m3_k<64><<<dim3(16, 1, 32), blk>>>(A, dt_w2, dt_b2, out + 1);
}

// round 14
// speedup vs baseline: 1.1431x; 1.0238x over previous
#include <cuda_runtime.h>
#include <math.h>

// ---------------------------------------------------------------------------
// VQ-VAE forward, fp32. Round 14: R11 base (e3 split reverted); res-stack
// 1x1 path factored: presum_k sums 4 partial chunks + relu ONCE (into Bf),
// conv1r8s_k reads the summed buffer (4x less partial traffic).
// Output layout: [loss, x_recon(1572864), perplexity]
// ---------------------------------------------------------------------------

// Scratch (device globals; no allocation allowed)
__device__ float g_A[32u * 64 * 64 * 64];    // e1 out / dt1 out / res partials
__device__ float g_B[32u * 128 * 32 * 32];   // e2 out / res chunk-sum buffer
__device__ float g_C[32u * 128 * 32 * 32];   // e3 out + encoder res stack
__device__ float g_Z[32u * 64 * 32 * 32];    // pre-VQ z
__device__ float g_Q[32u * 64 * 32 * 32];    // quantized q
__device__ float g_G[32u * 128 * 32 * 32];   // decoder stack
__device__ int   g_idx[32768];
__device__ float g_cnorm[512];
__device__ float g_err[32768];

// ---------------------------------------------------------------------------
// Generic direct conv (R2, proven): used for e1 (k4s2) and pre (1x1).
// ---------------------------------------------------------------------------
template <int KH, int KW, int S, int P, int TCO,
          int CIN, int HIN, int WIN, int COUT, int HOUT, int WOUT,
          bool IN_RELU, bool OUT_RELU, bool BIAS, bool ADD>
__global__ __launch_bounds__(128)
void conv_k(const float* __restrict__ in, const float* __restrict__ wt,
            const float* __restrict__ bs, float* __restrict__ out,
            const float* __restrict__ res)
{
    constexpr int TX   = 8;
    constexpr int WINW = (TX - 1) * S + KW;
    static_assert((HOUT * WOUT / TX) % 128 == 0, "tiles fill blocks");

    int tid = blockIdx.x * 128 + threadIdx.x;
    int ox0 = (tid * TX) % WOUT;
    int oy  = (tid * TX) / WOUT;
    int co0 = blockIdx.y * TCO;
    int b   = blockIdx.z;

    float acc[TCO][TX];
#pragma unroll
    for (int c = 0; c < TCO; c++) {
        float bv = BIAS ? __ldg(bs + co0 + c) : 0.f;
#pragma unroll
        for (int j = 0; j < TX; j++) acc[c][j] = bv;
    }

    const float* inb = in + (size_t)b * CIN * HIN * WIN;
    const int ixb = ox0 * S - P;

#pragma unroll 1
    for (int ci = 0; ci < CIN; ci++) {
        const float* ip  = inb + ci * HIN * WIN;
        const float* wci = wt + ((size_t)co0 * CIN + ci) * KH * KW;
#pragma unroll
        for (int ky = 0; ky < KH; ky++) {
            int iy = oy * S - P + ky;
            if (P > 0 && (iy < 0 || iy >= HIN)) continue;
            const float* row = ip + iy * WIN;
            float w[WINW];
            if constexpr (P == 0) {
                float4 v0 = *(const float4*)(row + ox0);
                float4 v1 = *(const float4*)(row + ox0 + 4);
                w[0] = v0.x; w[1] = v0.y; w[2] = v0.z; w[3] = v0.w;
                w[4] = v1.x; w[5] = v1.y; w[6] = v1.z; w[7] = v1.w;
            } else {
                w[0] = (ixb >= 0) ? row[ixb] : 0.f;
#pragma unroll
                for (int m = 0; m < (WINW - 2) / 4; m++) {
                    float4 v = *(const float4*)(row + ixb + 1 + 4 * m);
                    w[1 + 4 * m] = v.x; w[2 + 4 * m] = v.y;
                    w[3 + 4 * m] = v.z; w[4 + 4 * m] = v.w;
                }
                w[WINW - 1] = (ixb + WINW - 1 < WIN) ? row[ixb + WINW - 1] : 0.f;
            }
            if (IN_RELU) {
#pragma unroll
                for (int m = 0; m < WINW; m++) w[m] = fmaxf(w[m], 0.f);
            }
#pragma unroll
            for (int c = 0; c < TCO; c++) {
                const float* wp = wci + c * CIN * KH * KW + ky * KW;
                if constexpr (KW == 4) {
                    float4 wv = *(const float4*)wp;
                    float wk[4] = {wv.x, wv.y, wv.z, wv.w};
#pragma unroll
                    for (int kx = 0; kx < 4; kx++)
#pragma unroll
                        for (int j = 0; j < TX; j++)
                            acc[c][j] = fmaf(w[j * S + kx], wk[kx], acc[c][j]);
                } else {
#pragma unroll
                    for (int kx = 0; kx < KW; kx++) {
                        float wv = __ldg(wp + kx);
#pragma unroll
                        for (int j = 0; j < TX; j++)
                            acc[c][j] = fmaf(w[j * S + kx], wv, acc[c][j]);
                    }
                }
            }
        }
    }

#pragma unroll
    for (int c = 0; c < TCO; c++) {
        size_t o = (((size_t)b * COUT + (co0 + c)) * HOUT + oy) * WOUT + ox0;
        float v[TX];
#pragma unroll
        for (int j = 0; j < TX; j++) v[j] = acc[c][j];
        if (ADD) {
            float4 r0 = *(const float4*)(res + o);
            float4 r1 = *(const float4*)(res + o + 4);
            v[0] += r0.x; v[1] += r0.y; v[2] += r0.z; v[3] += r0.w;
            v[4] += r1.x; v[5] += r1.y; v[6] += r1.z; v[7] += r1.w;
        }
        if (OUT_RELU) {
#pragma unroll
            for (int j = 0; j < TX; j++) v[j] = fmaxf(v[j], 0.f);
        }
        *(float4*)(out + o)     = make_float4(v[0], v[1], v[2], v[3]);
        *(float4*)(out + o + 4) = make_float4(v[4], v[5], v[6], v[7]);
    }
}

// ---------------------------------------------------------------------------
// Smem-staged 3x3 s1 p1 conv on 32x32 maps (R8, proven).
// ---------------------------------------------------------------------------
template <int CINC, int CIN_TOTAL, int COUT, int NCH, bool IN_RELU, bool BIAS>
__global__ __launch_bounds__(128)
void conv3m_k(const float* __restrict__ in, const float* __restrict__ wt,
              const float* __restrict__ bs, float* __restrict__ out)
{
    __shared__ float sW[4 * 36];          // current 4 ci: [q][c*9 + tap]
    __shared__ float sI[4 * 36 * 32];     // 4 channels, rows padded to 36

    const int t     = threadIdx.x;
    const int ox0   = (t & 3) * 8;
    const int oy    = t >> 2;
    const int chunk = blockIdx.x;
    const int co0   = blockIdx.y * 4;
    const int b     = blockIdx.z;
    const int ci0   = chunk * CINC;

    float acc[4][8];
#pragma unroll
    for (int c = 0; c < 4; c++) {
        float bv = (NCH == 1 && BIAS) ? __ldg(bs + co0 + c) : 0.f;
#pragma unroll
        for (int j = 0; j < 8; j++) acc[c][j] = bv;
    }

    const float* inb = in + ((size_t)b * CIN_TOTAL + ci0) * 1024;

#pragma unroll 1
    for (int cc = 0; cc < CINC; cc += 4) {
        __syncthreads();
#pragma unroll
        for (int m = 0; m < 8; m++) {
            int idx = m * 128 + t;
            int q   = idx >> 8;
            int rem = idx & 255;
            int y   = rem >> 3;
            int xg  = (rem & 7) * 4;
            float4 v = *(const float4*)(inb + (cc + q) * 1024 + y * 32 + xg);
            if (IN_RELU) {
                v.x = fmaxf(v.x, 0.f); v.y = fmaxf(v.y, 0.f);
                v.z = fmaxf(v.z, 0.f); v.w = fmaxf(v.w, 0.f);
            }
            *(float4*)(sI + q * 1152 + y * 36 + xg) = v;
        }
        for (int i = t; i < 144; i += 128) {
            int q   = i / 36;
            int r   = i - q * 36;
            int c   = r / 9;
            int tap = r - c * 9;
            sW[i] =
                __ldg(wt + ((size_t)(co0 + c) * CIN_TOTAL + ci0 + cc + q) * 9 + tap);
        }
        __syncthreads();

#pragma unroll
        for (int q = 0; q < 4; q++) {
            const float* sw = sW + q * 36;
            const float* si = sI + q * 1152;
#pragma unroll
            for (int ky = 0; ky < 3; ky++) {
                int iy = oy - 1 + ky;
                if (iy < 0 || iy >= 32) continue;
                const float* row = si + iy * 36;
                float w[10];
                w[0] = (ox0 > 0) ? row[ox0 - 1] : 0.f;
                float4 v0 = *(const float4*)(row + ox0);
                float4 v1 = *(const float4*)(row + ox0 + 4);
                w[1] = v0.x; w[2] = v0.y; w[3] = v0.z; w[4] = v0.w;
                w[5] = v1.x; w[6] = v1.y; w[7] = v1.z; w[8] = v1.w;
                w[9] = (ox0 < 24) ? row[ox0 + 8] : 0.f;
#pragma unroll
                for (int c = 0; c < 4; c++) {
                    float w0 = sw[c * 9 + ky * 3];
                    float w1 = sw[c * 9 + ky * 3 + 1];
                    float w2 = sw[c * 9 + ky * 3 + 2];
#pragma unroll
                    for (int j = 0; j < 8; j++) {
                        acc[c][j] = fmaf(w[j],     w0, acc[c][j]);
                        acc[c][j] = fmaf(w[j + 1], w1, acc[c][j]);
                        acc[c][j] = fmaf(w[j + 2], w2, acc[c][j]);
                    }
                }
            }
        }
    }

#pragma unroll
    for (int c = 0; c < 4; c++) {
        size_t o;
        if (NCH == 1)
            o = (((size_t)b * COUT + (co0 + c)) * 32 + oy) * 32 + ox0;
        else
            o = (((size_t)(b * NCH + chunk) * COUT + (co0 + c)) * 32 + oy) * 32 + ox0;
        *(float4*)(out + o)     = make_float4(acc[c][0], acc[c][1], acc[c][2], acc[c][3]);
        *(float4*)(out + o + 4) = make_float4(acc[c][4], acc[c][5], acc[c][6], acc[c][7]);
    }
}

// ---------------------------------------------------------------------------
// NEW: presum 4 res3x3 partial chunks + relu -> summed [b][32ci][1024].
// Pure streaming kernel (reads 16MB, writes 4MB).
// ---------------------------------------------------------------------------
__global__ __launch_bounds__(256)
void presum_k(const float* __restrict__ part, float* __restrict__ dst)
{
    int i4 = blockIdx.x * 256 + threadIdx.x;
    if (i4 >= 262144) return;                 // 32*32*1024 / 4
    size_t f = (size_t)i4 * 4;
    int b = (int)(f >> 15);                   // / 32768
    size_t rem = f & 32767;
    const float* p = part + (size_t)(b * 4) * 32768 + rem;
    float4 s = make_float4(0.f, 0.f, 0.f, 0.f);
#pragma unroll
    for (int ch = 0; ch < 4; ch++) {
        float4 v = *(const float4*)(p + (size_t)ch * 32768);
        s.x += v.x; s.y += v.y; s.z += v.z; s.w += v.w;
    }
    s.x = fmaxf(s.x, 0.f); s.y = fmaxf(s.y, 0.f);
    s.z = fmaxf(s.z, 0.f); s.w = fmaxf(s.w, 0.f);
    *(float4*)(dst + (size_t)b * 32768 + rem) = s;
}

// ---------------------------------------------------------------------------
// Fused 1x1 (32->128) on PRE-SUMMED (relu'd) buffer + residual add.
// ---------------------------------------------------------------------------
__global__ __launch_bounds__(128)
void conv1r8s_k(const float* __restrict__ sum, const float* __restrict__ wt,
                const float* __restrict__ res, float* __restrict__ out)
{
    __shared__ float sW[8 * 32];

    const int t   = threadIdx.x;
    const int ox0 = (t & 3) * 8;
    const int oy  = t >> 2;
    const int co0 = blockIdx.y * 8;
    const int b   = blockIdx.z;

    for (int i = t; i < 256; i += 128)
        sW[i] = __ldg(wt + (co0 + (i >> 5)) * 32 + (i & 31));
    __syncthreads();

    float acc[8][8];
#pragma unroll
    for (int c = 0; c < 8; c++)
#pragma unroll
        for (int j = 0; j < 8; j++) acc[c][j] = 0.f;

    const float* pb = sum + (size_t)b * 32768 + oy * 32 + ox0;

#pragma unroll 1
    for (int ci = 0; ci < 32; ci++) {
        const float* p = pb + ci * 1024;
        float4 v0 = *(const float4*)p;
        float4 v1 = *(const float4*)(p + 4);
        float w[8] = {v0.x, v0.y, v0.z, v0.w, v1.x, v1.y, v1.z, v1.w};
#pragma unroll
        for (int c = 0; c < 8; c++) {
            float wv = sW[c * 32 + ci];
#pragma unroll
            for (int j = 0; j < 8; j++)
                acc[c][j] = fmaf(w[j], wv, acc[c][j]);
        }
    }

#pragma unroll
    for (int c = 0; c < 8; c++) {
        size_t o = (((size_t)b * 128 + (co0 + c)) * 32 + oy) * 32 + ox0;
        float4 r0 = *(const float4*)(res + o);
        float4 r1 = *(const float4*)(res + o + 4);
        *(float4*)(out + o) = make_float4(acc[c][0] + r0.x, acc[c][1] + r0.y,
                                          acc[c][2] + r0.z, acc[c][3] + r0.w);
        *(float4*)(out + o + 4) = make_float4(acc[c][4] + r1.x, acc[c][5] + r1.y,
                                              acc[c][6] + r1.z, acc[c][7] + r1.w);
    }
}

// ---------------------------------------------------------------------------
// Smem-staged k4 s2 p1 conv (e2) (R9, proven).
// ---------------------------------------------------------------------------
template <int CIN, int COUT>
__global__ __launch_bounds__(128)
void conv4m_k(const float* __restrict__ in, const float* __restrict__ wt,
              const float* __restrict__ bs, float* __restrict__ out)
{
    __shared__ float sI[66 * 68];
    __shared__ float sW[64];

    const int t   = threadIdx.x;
    const int ox0 = (t & 3) * 8;
    const int oy  = t >> 2;
    const int co0 = blockIdx.y * 4;
    const int b   = blockIdx.z;
    const int ixb = ox0 * 2 - 1;

    for (int i = t; i < (66 * 68) / 4; i += 128)
        *(float4*)(sI + i * 4) = make_float4(0.f, 0.f, 0.f, 0.f);

    float acc[4][8];
#pragma unroll
    for (int c = 0; c < 4; c++) {
        float bv = __ldg(bs + co0 + c);
#pragma unroll
        for (int j = 0; j < 8; j++) acc[c][j] = bv;
    }

    const float* inb = in + (size_t)b * CIN * 4096;

#pragma unroll 1
    for (int ci = 0; ci < CIN; ci++) {
        __syncthreads();
        const float* ip = inb + ci * 4096;
#pragma unroll
        for (int m = 0; m < 8; m++) {
            int idx = m * 128 + t;
            int y   = idx >> 4;
            int xg  = (idx & 15) * 4;
            float4 v = *(const float4*)(ip + y * 64 + xg);
            *(float4*)(sI + (y + 1) * 68 + xg) = v;
        }
        if (t < 16) {
            int c  = t >> 2;
            int ky = t & 3;
            *(float4*)(sW + t * 4) =
                *(const float4*)(wt + ((size_t)(co0 + c) * CIN + ci) * 16 + ky * 4);
        }
        __syncthreads();

#pragma unroll
        for (int ky = 0; ky < 4; ky++) {
            const float* row = sI + (oy * 2 + ky) * 68;
            float w[18];
            w[0] = (ox0 > 0) ? row[ixb] : 0.f;
#pragma unroll
            for (int m = 0; m < 4; m++) {
                float4 v = *(const float4*)(row + 2 * ox0 + 4 * m);
                w[1 + 4 * m] = v.x; w[2 + 4 * m] = v.y;
                w[3 + 4 * m] = v.z; w[4 + 4 * m] = v.w;
            }
            w[17] = row[ixb + 17];
#pragma unroll
            for (int c = 0; c < 4; c++) {
                float4 wv = *(const float4*)(sW + (c * 4 + ky) * 4);
                float wk[4] = {wv.x, wv.y, wv.z, wv.w};
#pragma unroll
                for (int kx = 0; kx < 4; kx++)
#pragma unroll
                    for (int j = 0; j < 8; j++)
                        acc[c][j] = fmaf(w[j * 2 + kx], wk[kx], acc[c][j]);
            }
        }
    }

#pragma unroll
    for (int c = 0; c < 4; c++) {
        size_t o = (((size_t)b * COUT + (co0 + c)) * 32 + oy) * 32 + ox0;
        float v[8];
#pragma unroll
        for (int j = 0; j < 8; j++) v[j] = fmaxf(acc[c][j], 0.f);
        *(float4*)(out + o)     = make_float4(v[0], v[1], v[2], v[3]);
        *(float4*)(out + o + 4) = make_float4(v[4], v[5], v[6], v[7]);
    }
}

// ---------------------------------------------------------------------------
// Smem-staged ConvTranspose2d(k=4,s=2,p=1) for dt1 (R9, proven).
// ---------------------------------------------------------------------------
template <int CIN, int COUT>
__global__ __launch_bounds__(128)
void dc4m_k(const float* __restrict__ in, const float* __restrict__ wt,
            const float* __restrict__ bs, float* __restrict__ out)
{
    __shared__ float sI[4 * 360];
    __shared__ float sW[4 * 64];

    const int t   = threadIdx.x;
    const int bx  = blockIdx.x;
    const int ox0 = (t & 7) * 8;
    const int oy  = bx * 16 + (t >> 3);
    const int co0 = blockIdx.y * 4;
    const int b   = blockIdx.z;
    const int iy0 = bx * 8 - 1;
    const int ixb = ox0 / 2 - 1;
    const int oyp = oy & 1;

    float acc[4][8];
#pragma unroll
    for (int c = 0; c < 4; c++) {
        float bv = __ldg(bs + co0 + c);
#pragma unroll
        for (int j = 0; j < 8; j++) acc[c][j] = bv;
    }

    const float* inb = in + (size_t)b * CIN * 1024;

#pragma unroll 1
    for (int cc = 0; cc < CIN; cc += 4) {
        __syncthreads();
        for (int i = t; i < 360; i += 128) {
            int q   = i / 90;
            int rem = i - q * 90;
            int r   = rem / 9;
            int xf  = rem - r * 9;
            int iy  = iy0 + r;
            float4 v = make_float4(0.f, 0.f, 0.f, 0.f);
            if (xf < 8 && iy >= 0 && iy < 32) {
                v = *(const float4*)(inb + (cc + q) * 1024 + iy * 32 + xf * 4);
                v.x = fmaxf(v.x, 0.f); v.y = fmaxf(v.y, 0.f);
                v.z = fmaxf(v.z, 0.f); v.w = fmaxf(v.w, 0.f);
            }
            *(float4*)(sI + q * 360 + r * 36 + xf * 4) = v;
        }
        for (int i = t; i < 64; i += 128) {
            int q  = i >> 4;
            int rm = i & 15;
            int c  = rm >> 2;
            int ky = rm & 3;
            *(float4*)(sW + i * 4) =
                *(const float4*)(wt + ((size_t)(co0 + c) * CIN + cc + q) * 16 + ky * 4);
        }
        __syncthreads();

#pragma unroll
        for (int q = 0; q < 4; q++) {
            const float* si = sI + q * 360;
#pragma unroll
            for (int tt = 0; tt < 2; tt++) {
                int ky = oyp + 2 * tt;
                int r  = ((oy - 2 + ky) >> 1) - iy0;
                const float* row = si + r * 36;
                float u[6];
                u[0] = (ixb >= 0) ? row[ixb] : 0.f;
                float4 v = *(const float4*)(row + ixb + 1);
                u[1] = v.x; u[2] = v.y; u[3] = v.z; u[4] = v.w;
                u[5] = row[ixb + 5];
#pragma unroll
                for (int c = 0; c < 4; c++) {
                    float4 wv = *(const float4*)(sW + (q * 16 + c * 4 + ky) * 4);
#pragma unroll
                    for (int j = 0; j < 8; j++) {
                        const int jo = j & 1;
                        const int sh = (j + 1) >> 1;
                        float wl = jo ? wv.y : wv.x;
                        float wh = jo ? wv.w : wv.z;
                        acc[c][j] = fmaf(u[sh],     wl, acc[c][j]);
                        acc[c][j] = fmaf(u[sh + 1], wh, acc[c][j]);
                    }
                }
            }
        }
    }

#pragma unroll
    for (int c = 0; c < 4; c++) {
        size_t o = (((size_t)b * COUT + (co0 + c)) * 64 + oy) * 64 + ox0;
        float v[8];
#pragma unroll
        for (int j = 0; j < 8; j++) v[j] = fmaxf(acc[c][j], 0.f);
        *(float4*)(out + o)     = make_float4(v[0], v[1], v[2], v[3]);
        *(float4*)(out + o + 4) = make_float4(v[4], v[5], v[6], v[7]);
    }
}

// ---------------------------------------------------------------------------
// Smem-staged ConvTranspose2d(k=4,s=2,p=1) for dt2 (R10, proven).
// ---------------------------------------------------------------------------
template <int CIN>
__global__ __launch_bounds__(128)
void dc4m3_k(const float* __restrict__ in, const float* __restrict__ wt,
             const float* __restrict__ bs, float* __restrict__ out)
{
    __shared__ float sI[4 * 408];
    __shared__ float sW[4 * 48];

    const int t   = threadIdx.x;
    const int bx  = blockIdx.x;
    const int ox0 = (t & 15) * 8;
    const int oy  = bx * 8 + (t >> 4);
    const int b   = blockIdx.z;
    const int iy0 = bx * 4 - 1;
    const int ixb = ox0 / 2 - 1;
    const int oyp = oy & 1;

    float acc[3][8];
#pragma unroll
    for (int c = 0; c < 3; c++) {
        float bv = __ldg(bs + c);
#pragma unroll
        for (int j = 0; j < 8; j++) acc[c][j] = bv;
    }

    const float* inb = in + (size_t)b * CIN * 4096;

#pragma unroll 1
    for (int cc = 0; cc < CIN; cc += 4) {
        __syncthreads();
        for (int i = t; i < 408; i += 128) {
            int q   = i / 102;
            int rem = i - q * 102;
            int r   = rem / 17;
            int xf  = rem - r * 17;
            int iy  = iy0 + r;
            float4 v = make_float4(0.f, 0.f, 0.f, 0.f);
            if (xf < 16 && iy >= 0 && iy < 64)
                v = *(const float4*)(inb + (cc + q) * 4096 + iy * 64 + xf * 4);
            *(float4*)(sI + q * 408 + r * 68 + xf * 4) = v;
        }
        for (int i = t; i < 48; i += 128) {
            int q  = i / 12;
            int rm = i - q * 12;
            int c  = rm >> 2;
            int ky = rm & 3;
            *(float4*)(sW + (q * 48 + c * 16 + ky * 4)) =
                *(const float4*)(wt + ((size_t)c * CIN + cc + q) * 16 + ky * 4);
        }
        __syncthreads();

#pragma unroll
        for (int q = 0; q < 4; q++) {
            const float* si = sI + q * 408;
#pragma unroll
            for (int tt = 0; tt < 2; tt++) {
                int ky = oyp + 2 * tt;
                int r  = ((oy - 2 + ky) >> 1) - iy0;
                const float* row = si + r * 68;
                float u[6];
                u[0] = (ixb >= 0) ? row[ixb] : 0.f;
                float4 v = *(const float4*)(row + ixb + 1);
                u[1] = v.x; u[2] = v.y; u[3] = v.z; u[4] = v.w;
                u[5] = row[ixb + 5];
#pragma unroll
                for (int c = 0; c < 3; c++) {
                    float4 wv = *(const float4*)(sW + q * 48 + c * 16 + ky * 4);
#pragma unroll
                    for (int j = 0; j < 8; j++) {
                        const int jo = j & 1;
                        const int sh = (j + 1) >> 1;
                        float wl = jo ? wv.y : wv.x;
                        float wh = jo ? wv.w : wv.z;
                        acc[c][j] = fmaf(u[sh],     wl, acc[c][j]);
                        acc[c][j] = fmaf(u[sh + 1], wh, acc[c][j]);
                    }
                }
            }
        }
    }

#pragma unroll
    for (int c = 0; c < 3; c++) {
        size_t o = (((size_t)b * 3 + c) * 128 + oy) * 128 + ox0;
#pragma unroll
        for (int j = 0; j < 8; j++) out[o + j] = acc[c][j];
    }
}

// ---------------------------------------------------------------------------
// VQ (R2, proven)
// ---------------------------------------------------------------------------
__global__ void cnorm_kernel(const float* __restrict__ cb, float* __restrict__ cn)
{
    int k = blockIdx.x * blockDim.x + threadIdx.x;
    if (k >= 512) return;
    const float* c = cb + k * 64;
    float s = 0.f;
#pragma unroll
    for (int d = 0; d < 64; d++) s = fmaf(c[d], c[d], s);
    cn[k] = s;
}

__global__ __launch_bounds__(128)
void vq_kernel(const float* __restrict__ z, const float* __restrict__ cb,
               const float* __restrict__ cn, int* __restrict__ idx,
               float* __restrict__ q, float* __restrict__ err)
{
    int p = blockIdx.x * blockDim.x + threadIdx.x;  // 0..32767
    if (p >= 32768) return;
    int b = p >> 10, s = p & 1023;
    const float* zp = z + (size_t)b * 64 * 1024 + s;
    float zv[64];
#pragma unroll
    for (int d = 0; d < 64; d++) zv[d] = zp[d * 1024];

    float best = 3.4e38f;
    int bk = 0;
#pragma unroll 1
    for (int k = 0; k < 512; k++) {
        const float4* c4 = (const float4*)(cb + (size_t)k * 64);
        float d0 = 0.f, d1 = 0.f, d2 = 0.f, d3 = 0.f;
#pragma unroll
        for (int m = 0; m < 16; m++) {
            float4 cv = __ldg(c4 + m);
            d0 = fmaf(zv[4 * m],     cv.x, d0);
            d1 = fmaf(zv[4 * m + 1], cv.y, d1);
            d2 = fmaf(zv[4 * m + 2], cv.z, d2);
            d3 = fmaf(zv[4 * m + 3], cv.w, d3);
        }
        float dist = __ldg(cn + k) - 2.f * ((d0 + d1) + (d2 + d3));
        if (dist < best) { best = dist; bk = k; }   // strict <: first-min (jnp.argmin)
    }
    idx[p] = bk;
    float* qp = q + (size_t)b * 64 * 1024 + s;
    const float* c = cb + (size_t)bk * 64;
    float e = 0.f;
#pragma unroll
    for (int d = 0; d < 64; d++) {
        float cd = __ldg(c + d);
        qp[d * 1024] = cd;
        float df = zv[d] - cd;
        e = fmaf(df, df, e);
    }
    err[p] = e;
}

__global__ __launch_bounds__(512)
void stats_kernel(const int* __restrict__ idx, const float* __restrict__ err,
                  float* __restrict__ out0, float* __restrict__ outp)
{
    __shared__ int   h[512];
    __shared__ float sm[512];
    int t = threadIdx.x;
    h[t] = 0;
    float s = 0.f;
    __syncthreads();
    for (int i = t; i < 32768; i += 512) {
        atomicAdd(&h[idx[i]], 1);
        s += err[i];
    }
    sm[t] = s;
    __syncthreads();
    for (int off = 256; off > 0; off >>= 1) {
        if (t < off) sm[t] += sm[t + off];
        __syncthreads();
    }
    if (t == 0) out0[0] = 1.25f * sm[0] / 2097152.0f;   // (1+beta)*mse
    __syncthreads();
    float pr = (float)h[t] * (1.0f / 32768.0f);
    sm[t] = pr * logf(pr + 1e-10f);
    __syncthreads();
    for (int off = 256; off > 0; off >>= 1) {
        if (t < off) sm[t] += sm[t + off];
        __syncthreads();
    }
    if (t == 0) outp[0] = expf(-sm[0]);
}

// ---------------------------------------------------------------------------
// Launch
// ---------------------------------------------------------------------------
extern "C" void kernel_launch(void* const* d_in, const int* in_sizes, int n_in,
                              void* d_out, int out_size)
{
    const float* x     = (const float*)d_in[0];
    const float* e_w1  = (const float*)d_in[1];
    const float* e_b1  = (const float*)d_in[2];
    const float* e_w2  = (const float*)d_in[3];
    const float* e_b2  = (const float*)d_in[4];
    const float* e_w3  = (const float*)d_in[5];
    const float* e_b3  = (const float*)d_in[6];
    const float* e_r1a = (const float*)d_in[7];
    const float* e_r1b = (const float*)d_in[8];
    const float* e_r2a = (const float*)d_in[9];
    const float* e_r2b = (const float*)d_in[10];
    const float* pre_w = (const float*)d_in[11];
    const float* pre_b = (const float*)d_in[12];
    const float* cb    = (const float*)d_in[13];
    const float* d_w1  = (const float*)d_in[14];
    const float* d_b1  = (const float*)d_in[15];
    const float* d_r1a = (const float*)d_in[16];
    const float* d_r1b = (const float*)d_in[17];
    const float* d_r2a = (const float*)d_in[18];
    const float* d_r2b = (const float*)d_in[19];
    const float* dt_w1 = (const float*)d_in[20];
    const float* dt_b1 = (const float*)d_in[21];
    const float* dt_w2 = (const float*)d_in[22];
    const float* dt_b2 = (const float*)d_in[23];
    float* out = (float*)d_out;

    float *A, *Bf, *Cc, *Z, *Q, *G, *cn, *err;
    int *idx;
    cudaGetSymbolAddress((void**)&A,    g_A);
    cudaGetSymbolAddress((void**)&Bf,   g_B);
    cudaGetSymbolAddress((void**)&Cc,   g_C);
    cudaGetSymbolAddress((void**)&Z,    g_Z);
    cudaGetSymbolAddress((void**)&Q,    g_Q);
    cudaGetSymbolAddress((void**)&G,    g_G);
    cudaGetSymbolAddress((void**)&cn,   g_cnorm);
    cudaGetSymbolAddress((void**)&err,  g_err);
    cudaGetSymbolAddress((void**)&idx,  g_idx);

    dim3 blk(128);

    // ---- encoder ----
    conv_k<4,4,2,1,4, 3,128,128, 64,64,64, false,true,true,false>
        <<<dim3(4, 16, 32), blk>>>(x, e_w1, e_b1, A, nullptr);
    conv4m_k<64, 128><<<dim3(1, 32, 32), blk>>>(A, e_w2, e_b2, Bf);
    // e3 (unsplit, R11): Bf -> Cc (bias, no relu). Bf is free afterwards.
    conv3m_k<128, 128, 128, 1, false, true>
        <<<dim3(1, 32, 32), blk>>>(Bf, e_w3, e_b3, Cc);
    // encoder res stack (x2): split-4 3x3 -> A partials; presum -> Bf; 1x1
    conv3m_k<32, 128, 32, 4, true, false>
        <<<dim3(4, 8, 32), blk>>>(Cc, e_r1a, nullptr, A);
    presum_k<<<1024, 256>>>(A, Bf);
    conv1r8s_k<<<dim3(1, 16, 32), blk>>>(Bf, e_r1b, Cc, Cc);
    conv3m_k<32, 128, 32, 4, true, false>
        <<<dim3(4, 8, 32), blk>>>(Cc, e_r2a, nullptr, A);
    presum_k<<<1024, 256>>>(A, Bf);
    conv1r8s_k<<<dim3(1, 16, 32), blk>>>(Bf, e_r2b, Cc, Cc);
    conv_k<1,1,1,0,4, 128,32,32, 64,32,32, true,false,true,false>
        <<<dim3(1, 16, 32), blk>>>(Cc, pre_w, pre_b, Z, nullptr);

    // ---- vector quantizer ----
    cnorm_kernel<<<2, 256>>>(cb, cn);
    vq_kernel<<<256, 128>>>(Z, cb, cn, idx, Q, err);
    stats_kernel<<<1, 512>>>(idx, err, out, out + (out_size - 1));

    // ---- decoder ----
    conv3m_k<64, 64, 128, 1, false, true>
        <<<dim3(1, 32, 32), blk>>>(Q, d_w1, d_b1, G);
    conv3m_k<32, 128, 32, 4, true, false>
        <<<dim3(4, 8, 32), blk>>>(G, d_r1a, nullptr, A);
    presum_k<<<1024, 256>>>(A, Bf);
    conv1r8s_k<<<dim3(1, 16, 32), blk>>>(Bf, d_r1b, G, G);
    conv3m_k<32, 128, 32, 4, true, false>
        <<<dim3(4, 8, 32), blk>>>(G, d_r2a, nullptr, A);
    presum_k<<<1024, 256>>>(A, Bf);
    conv1r8s_k<<<dim3(1, 16, 32), blk>>>(Bf, d_r2b, G, G);
    dc4m_k<128, 64><<<dim3(4, 16, 32), blk>>>(G, dt_w1, dt_b1, A);
    dc4m3_k<64><<<dim3(16, 1, 32), blk>>>(A, dt_w2, dt_b2, out + 1);
}